// round 17
// baseline (speedup 1.0000x reference)
#include <cuda_runtime.h>
#include <math.h>
#include <stdint.h>

// Problem constants (LMUCell: B=32, T=2048, D=128, U=512, N=256)
#define Bsz  32
#define Tn   2048
#define Dn   128
#define Un   512
#define Nn   256
#define KTOT 896     // D + U + N
#define OTOT 768     // U + N
#define GRID 128     // 32 column-groups x 4 batch-groups
#define TPB  512     // 16 warps = 4 pair-blocks x 4 k-quarters

typedef unsigned long long u64t;

// ---------------- device scratch (static, no allocation) ----------------
__device__ float g_W1[Nn * Un];                    // (I+AT) @ Wmh
__device__ float g_w2[Un];                         // BT @ Wmh
__device__ float g_WT[OTOT * KTOT];                // WbigT[u][k]
// state: [buf][bg(4)][k(768)][b(8)] plain float
__device__ __align__(16) float g_state[2][4 * OTOT * 8];
// x transposed: [bg(4)][t][k(128)][b(8)]
__device__ __align__(16) float g_xt[(size_t)4 * Tn * Dn * 8];   // 33 MB
__device__ unsigned g_arrive[GRID * 32];           // per-CTA flags, 128B apart

// ---------------- f32x2 helpers ----------------
__device__ __forceinline__ u64t splat2(float a) {
    u64t r; unsigned au = __float_as_uint(a);
    asm("mov.b64 %0,{%1,%1};" : "=l"(r) : "r"(au));
    return r;
}
__device__ __forceinline__ u64t pack2(float a, float b) {
    u64t r; unsigned au = __float_as_uint(a), bu = __float_as_uint(b);
    asm("mov.b64 %0,{%1,%2};" : "=l"(r) : "r"(au), "r"(bu));
    return r;
}
__device__ __forceinline__ void fma2(u64t& d, u64t a, u64t b) {
    asm("fma.rn.f32x2 %0,%1,%2,%0;" : "+l"(d) : "l"(a), "l"(b));
}
__device__ __forceinline__ u64t add2(u64t a, u64t b) {
    u64t r;
    asm("add.rn.f32x2 %0,%1,%2;" : "=l"(r) : "l"(a), "l"(b));
    return r;
}
__device__ __forceinline__ void unpack2(u64t v, float& lo, float& hi) {
    unsigned a, b;
    asm("mov.b64 {%0,%1},%2;" : "=r"(a), "=r"(b) : "l"(v));
    lo = __uint_as_float(a); hi = __uint_as_float(b);
}

// ---------------- init0: transpose x -> [bg][t][k][b8] ----------------
__global__ void lmu_init0(const float* __restrict__ x) {
    size_t i = (size_t)blockIdx.x * blockDim.x + threadIdx.x;
    if (i >= (size_t)4 * Tn * Dn * 8) return;
    int b  = (int)(i & 7);
    int k  = (int)((i >> 3) & 127);
    int t  = (int)((i >> 10) & 2047);
    int bg = (int)(i >> 21);
    g_xt[i] = x[((size_t)(bg * 8 + b) * Tn + t) * Dn + k];
}

// ---------------- init1: W1, w2, state init, flag reset ----------------
__global__ void lmu_init1(const float* __restrict__ h0, const float* __restrict__ m0,
                          const float* __restrict__ Wmh, const float* __restrict__ AT,
                          const float* __restrict__ BT) {
    int i = blockIdx.x * blockDim.x + threadIdx.x;
    const int b1 = Nn * Un;
    const int b2 = b1 + Un;
    const int b3 = b2 + 4 * OTOT * 8;
    if (i < b1) {
        int j = i / Un, u = i % Un;
        float s = 0.f;
        #pragma unroll 4
        for (int q = 0; q < Nn; q++) {
            float a = AT[j * Nn + q] + (q == j ? 1.0f : 0.0f);
            s = fmaf(a, Wmh[q * Un + u], s);
        }
        g_W1[i] = s;
    } else if (i < b2) {
        int u = i - b1;
        float s = 0.f;
        #pragma unroll 4
        for (int q = 0; q < Nn; q++) s = fmaf(BT[q], Wmh[q * Un + u], s);
        g_w2[u] = s;
    } else if (i < b3) {
        int r  = i - b2;
        int b  = r & 7;
        int k  = (r >> 3) % OTOT;
        int bg = r / (OTOT * 8);
        int gb = bg * 8 + b;
        g_state[0][r] = (k < Un) ? h0[gb * Un + k] : m0[gb * Nn + (k - Un)];
    } else if (i < b3 + GRID) {
        g_arrive[(i - b3) * 32] = 0u;   // reset barrier flags (graph replays!)
    }
}

// ---------------- init2: build fused WbigT[u][k] ----------------
__global__ void lmu_init2(const float* __restrict__ ie, const float* __restrict__ he,
                          const float* __restrict__ me, const float* __restrict__ Wi,
                          const float* __restrict__ Whh, const float* __restrict__ AT,
                          const float* __restrict__ BT) {
    int i = blockIdx.x * blockDim.x + threadIdx.x;
    if (i >= OTOT * KTOT) return;
    int u = i / KTOT, k = i % KTOT;
    float v;
    if (u < Un) {
        float w2u = g_w2[u];
        if (k < Dn)            v = fmaf(ie[k], w2u, Wi[k * Un + u]);
        else if (k < Dn + Un) { int kk = k - Dn; v = fmaf(he[kk], w2u, Whh[kk * Un + u]); }
        else                  { int j  = k - Dn - Un; v = fmaf(me[j], w2u, g_W1[j * Un + u]); }
    } else {
        int n = u - Un; float btn = BT[n];
        if (k < Dn)            v = ie[k] * btn;
        else if (k < Dn + Un)  v = he[k - Dn] * btn;
        else { int j = k - Dn - Un; v = AT[j * Nn + n] + (j == n ? 1.0f : 0.0f) + me[j] * btn; }
    }
    g_WT[i] = v;
}

// ---------------- compute slice: JN j-iterations, weight-k base KB ----------------
// HX: first 4 j come from x (k in [0,128)); state index sk = KB - 128 + j*32 + lane.
template<int JN, int KB, bool HX>
__device__ __forceinline__ void compute_slice(u64t acc[3][8], const u64t w[3][8],
                                              const float* __restrict__ st,
                                              const float* __restrict__ xt,
                                              int lane) {
    #pragma unroll
    for (int j = 0; j < JN; j++) {
        float av[8];
        if (HX && j < 4) {
            const float4* xp = (const float4*)&xt[(size_t)(j * 32 + lane) * 8];
            float4 a = __ldg(xp), b = __ldg(xp + 1);
            av[0]=a.x; av[1]=a.y; av[2]=a.z; av[3]=a.w;
            av[4]=b.x; av[5]=b.y; av[6]=b.z; av[7]=b.w;
        } else {
            int sk = KB - 128 + j * 32 + lane;
            const float4* sp = (const float4*)&st[sk * 8];
            float4 a = __ldcg(sp), b = __ldcg(sp + 1);
            av[0]=a.x; av[1]=a.y; av[2]=a.z; av[3]=a.w;
            av[4]=b.x; av[5]=b.y; av[6]=b.z; av[7]=b.w;
        }
        #pragma unroll
        for (int b = 0; b < 8; b++) {
            u64t aa = splat2(av[b]);
            fma2(acc[0][b], aa, w[0][j]);
            fma2(acc[1][b], aa, w[1][j]);
            fma2(acc[2][b], aa, w[2][j]);
        }
    }
}

// ---------------- main persistent recurrence kernel ----------------
__global__ void __launch_bounds__(TPB, 1) lmu_main(float* __restrict__ out) {
    __shared__ u64t sRed[3][4][24];   // [kq 0..2][pb][p*8 + b]

    const int tid = threadIdx.x, c = blockIdx.x;
    const int cg = c & 31, bg = c >> 5;
    const int obase = cg * 24;

    const int warp = tid >> 5, lane = tid & 31;
    const int pb = warp >> 2;        // pair-block 0..3 (3 col-pairs each)
    const int kq = warp & 3;         // k-quarter
    // per-kq: j count and weight-k base
    const int jn = (kq == 0) ? 6 : (kq == 3) ? 8 : 7;
    const int kb = (kq == 0) ? 0 : (kq == 1) ? 192 : (kq == 2) ? 416 : 640;

    // ---- preload this warp's weight slice into registers (once) ----
    u64t w[3][8];
    {
        const int row0 = (obase + 2 * (pb * 3)) * KTOT;   // first col of pair 0
        #pragma unroll
        for (int p = 0; p < 3; p++) {
            const float* r0 = &g_WT[row0 + 2 * p * KTOT];
            const float* r1 = r0 + KTOT;
            #pragma unroll
            for (int j = 0; j < 8; j++) {
                int k = kb + j * 32 + lane;
                w[p][j] = (j < jn) ? pack2(r0[k], r1[k]) : 0ull;
            }
        }
    }
    __syncthreads();

    const float* xtb = g_xt + (size_t)bg * Tn * Dn * 8;

    for (int t = 0; t < Tn; t++) {
        const float* st = &g_state[t & 1][bg * OTOT * 8];
        const float* xt = &xtb[(size_t)t * Dn * 8];

        u64t acc[3][8];
        #pragma unroll
        for (int p = 0; p < 3; p++)
            #pragma unroll
            for (int b = 0; b < 8; b++) acc[p][b] = 0ull;

        if      (kq == 0) compute_slice<6, 0,   true >(acc, w, st, xt, lane);
        else if (kq == 1) compute_slice<7, 192, false>(acc, w, st, xt, lane);
        else if (kq == 2) compute_slice<7, 416, false>(acc, w, st, xt, lane);
        else              compute_slice<8, 640, false>(acc, w, st, xt, lane);

        // ---- reduce: level0 xor16 exchanges batch-halves (24 -> 12 live) ----
        u64t r[3][4];
        const bool hi = (lane & 16) != 0;
        #pragma unroll
        for (int p = 0; p < 3; p++)
            #pragma unroll
            for (int b = 0; b < 4; b++) {
                u64t t0 = __shfl_xor_sync(0xffffffffu, acc[p][b],     16);
                u64t t1 = __shfl_xor_sync(0xffffffffu, acc[p][b + 4], 16);
                r[p][b] = hi ? add2(acc[p][b + 4], t1) : add2(acc[p][b], t0);
            }
        #pragma unroll
        for (int m = 8; m; m >>= 1)
            #pragma unroll
            for (int p = 0; p < 3; p++)
                #pragma unroll
                for (int b = 0; b < 4; b++)
                    r[p][b] = add2(r[p][b], __shfl_xor_sync(0xffffffffu, r[p][b], m));

        // ---- each half-group lane selects its (p, b) value ----
        const int lid   = lane & 15;
        const int p_    = lid >> 2, b4_ = lid & 3;
        const int bglob = (hi ? 4 : 0) + b4_;
        const bool active = lid < 12;
        u64t mine = 0ull;
        if (active) {
            u64t rp0 = b4_==0 ? r[0][0] : b4_==1 ? r[0][1] : b4_==2 ? r[0][2] : r[0][3];
            u64t rp1 = b4_==0 ? r[1][0] : b4_==1 ? r[1][1] : b4_==2 ? r[1][2] : r[1][3];
            u64t rp2 = b4_==0 ? r[2][0] : b4_==1 ? r[2][1] : b4_==2 ? r[2][2] : r[2][3];
            mine = p_==0 ? rp0 : p_==1 ? rp1 : rp2;
        }
        const int ridx = p_ * 8 + bglob;
        if (kq < 3 && active) sRed[kq][pb][ridx] = mine;
        __syncthreads();                                    // A: partials visible

        float v0 = 0.f, v1 = 0.f; int o0 = 0; bool isH = false;
        float* stn = &g_state[(t + 1) & 1][bg * OTOT * 8];
        if (kq == 3 && active) {
            u64t s = add2(add2(mine, sRed[0][pb][ridx]),
                          add2(sRed[1][pb][ridx], sRed[2][pb][ridx]));
            unpack2(s, v0, v1);
            o0 = obase + (pb * 3 + p_) * 2;                 // even; no 512-straddle
            isH = (o0 < Un);
            if (isH) { v0 = tanhf(v0); v1 = tanhf(v1); }
            stn[o0 * 8 + bglob]       = v0;
            stn[(o0 + 1) * 8 + bglob] = v1;
        }
        __syncthreads();                                    // B: state stores done
        if (tid == 0) {
            asm volatile("st.global.release.gpu.u32 [%0], %1;"
                         :: "l"(&g_arrive[c * 32]), "r"((unsigned)(t + 1)) : "memory");
        }

        // ---- hidden behind barrier: out stores ----
        if (isH) {
            size_t ob = ((size_t)(bg * 8 + bglob) * Tn + t) * Un + o0;
            *(float2*)&out[ob] = make_float2(v0, v1);
        }

        // ---- wait: the 32 CTAs of THIS batch-group ----
        if (t + 1 < Tn) {
            if (tid < 32) {
                const unsigned* fp = &g_arrive[(bg * 32 + tid) * 32];
                unsigned v;
                do {
                    asm volatile("ld.global.acquire.gpu.u32 %0,[%1];" : "=r"(v) : "l"(fp));
                } while (v < (unsigned)(t + 1));
            }
            __syncthreads();                                // C
        }
    }
}

// ---------------- launch ----------------
extern "C" void kernel_launch(void* const* d_in, const int* in_sizes, int n_in,
                              void* d_out, int out_size) {
    const float* x   = (const float*)d_in[0];   // (32,2048,128)
    const float* h0  = (const float*)d_in[1];   // (32,512)
    const float* m0  = (const float*)d_in[2];   // (32,256)
    const float* ie  = (const float*)d_in[3];   // (128,1)
    const float* he  = (const float*)d_in[4];   // (512,1)
    const float* me  = (const float*)d_in[5];   // (256,1)
    const float* Wi  = (const float*)d_in[6];   // (128,512)
    const float* Whh = (const float*)d_in[7];   // (512,512)
    const float* Wmh = (const float*)d_in[8];   // (256,512)
    const float* AT  = (const float*)d_in[9];   // (256,256)
    const float* BT  = (const float*)d_in[10];  // (1,256)
    float* out = (float*)d_out;                 // (32,2048,512)

    // init0: transpose x to [bg][t][k][b8]
    size_t nx = (size_t)4 * Tn * Dn * 8;
    lmu_init0<<<(unsigned)((nx + 255) / 256), 256>>>(x);

    // init1: W1, w2, state[0], flags reset
    int n1 = Nn * Un + Un + 4 * OTOT * 8 + GRID;
    lmu_init1<<<(n1 + 255) / 256, 256>>>(h0, m0, Wmh, AT, BT);

    // init2: fused big weight matrix
    int n2 = OTOT * KTOT;
    lmu_init2<<<(n2 + 255) / 256, 256>>>(ie, he, me, Wi, Whh, AT, BT);

    // persistent recurrence
    lmu_main<<<GRID, TPB>>>(out);
}